// round 1
// baseline (speedup 1.0000x reference)
#include <cuda_runtime.h>

// ElementwiseTensorProd_o1: l=1 outputs of per-channel tensor product.
// Inputs (metadata order):
//   d_in[0] z_0_l : (N, RANK)        float32
//   d_in[1] z_1_l : (N, 3, RANK)     float32
//   d_in[2] z_0_r : (N, RANK)        float32
//   d_in[3] z_1_r : (N, 3, RANK)     float32
// Output: (N, 3, 3*RANK) float32, channel order [p01 | p10 | p11] per m.
//   p01_m = s_l * v_r[m]
//   p10_m = v_l[m] * s_r
//   p11_m = cross(v_l, v_r)[m] * (1/sqrt(2))

#define RANK 256
#define RQ   (RANK / 4)      // float4 groups per rank row = 64
#define OQ   (3 * RANK / 4)  // float4 groups per output row = 192

__device__ __forceinline__ float4 mul4(float4 a, float4 b) {
    return make_float4(a.x * b.x, a.y * b.y, a.z * b.z, a.w * b.w);
}
__device__ __forceinline__ float4 fms4(float4 a, float4 b, float4 c, float4 d, float s) {
    // (a*b - c*d) * s, elementwise
    return make_float4((a.x * b.x - c.x * d.x) * s,
                       (a.y * b.y - c.y * d.y) * s,
                       (a.z * b.z - c.z * d.z) * s,
                       (a.w * b.w - c.w * d.w) * s);
}

__global__ void __launch_bounds__(256)
etp_o1_kernel(const float4* __restrict__ z0l,
              const float4* __restrict__ z1l,
              const float4* __restrict__ z0r,
              const float4* __restrict__ z1r,
              float4* __restrict__ out,
              int n_total)  // N * RQ
{
    const float INV_SQRT2 = 0.7071067811865476f;
    int idx = blockIdx.x * blockDim.x + threadIdx.x;
    if (idx >= n_total) return;

    int n = idx / RQ;
    int r = idx - n * RQ;

    // Scalars
    float4 sl = z0l[n * RQ + r];
    float4 sr = z0r[n * RQ + r];

    // Vectors: (N, 3, RANK) -> row m at (n*3 + m)*RQ
    const float4* vl_base = z1l + (size_t)(n * 3) * RQ + r;
    const float4* vr_base = z1r + (size_t)(n * 3) * RQ + r;
    float4 vl0 = vl_base[0 * RQ];
    float4 vl1 = vl_base[1 * RQ];
    float4 vl2 = vl_base[2 * RQ];
    float4 vr0 = vr_base[0 * RQ];
    float4 vr1 = vr_base[1 * RQ];
    float4 vr2 = vr_base[2 * RQ];

    // Output: (N, 3, 3*RANK) -> row m at (n*3 + m)*OQ; paths at +0, +RQ, +2*RQ
    float4* ob = out + (size_t)(n * 3) * OQ + r;

    // m = 0
    ob[0 * OQ + 0 * RQ] = mul4(sl, vr0);
    ob[0 * OQ + 1 * RQ] = mul4(vl0, sr);
    ob[0 * OQ + 2 * RQ] = fms4(vl1, vr2, vl2, vr1, INV_SQRT2);
    // m = 1
    ob[1 * OQ + 0 * RQ] = mul4(sl, vr1);
    ob[1 * OQ + 1 * RQ] = mul4(vl1, sr);
    ob[1 * OQ + 2 * RQ] = fms4(vl2, vr0, vl0, vr2, INV_SQRT2);
    // m = 2
    ob[2 * OQ + 0 * RQ] = mul4(sl, vr2);
    ob[2 * OQ + 1 * RQ] = mul4(vl2, sr);
    ob[2 * OQ + 2 * RQ] = fms4(vl0, vr1, vl1, vr0, INV_SQRT2);
}

extern "C" void kernel_launch(void* const* d_in, const int* in_sizes, int n_in,
                              void* d_out, int out_size) {
    const float4* z0l = (const float4*)d_in[0];
    const float4* z1l = (const float4*)d_in[1];
    const float4* z0r = (const float4*)d_in[2];
    const float4* z1r = (const float4*)d_in[3];
    float4* out = (float4*)d_out;

    int N = in_sizes[0] / RANK;          // 50000
    int n_total = N * RQ;                // 3.2M float4-work-items
    int threads = 256;
    int blocks = (n_total + threads - 1) / threads;
    etp_o1_kernel<<<blocks, threads>>>(z0l, z1l, z0r, z1r, out, n_total);
}

// round 2
// speedup vs baseline: 1.0025x; 1.0025x over previous
#include <cuda_runtime.h>

// ElementwiseTensorProd_o1: l=1 outputs of per-channel tensor product.
//   p01_m = s_l * v_r[m]
//   p10_m = v_l[m] * s_r
//   p11_m = cross(v_l, v_r)[m] * (1/sqrt(2))
// Layout: inputs z0 (N,RANK), z1 (N,3,RANK); out (N,3,3*RANK) = [p01|p10|p11].
// Pure streaming, touch-once -> __ldcs/__stcs evict-first hints, 2 rows/thread.

#define RANK 256
#define RQ   (RANK / 4)      // 64 float4 groups per rank row
#define OQ   (3 * RANK / 4)  // 192 float4 groups per output row

__device__ __forceinline__ float4 ld4(const float4* p) { return __ldcs(p); }
__device__ __forceinline__ void   st4(float4* p, float4 v) { __stcs(p, v); }

__device__ __forceinline__ float4 mul4(float4 a, float4 b) {
    return make_float4(a.x * b.x, a.y * b.y, a.z * b.z, a.w * b.w);
}
__device__ __forceinline__ float4 fms4(float4 a, float4 b, float4 c, float4 d, float s) {
    return make_float4((a.x * b.x - c.x * d.x) * s,
                       (a.y * b.y - c.y * d.y) * s,
                       (a.z * b.z - c.z * d.z) * s,
                       (a.w * b.w - c.w * d.w) * s);
}

struct Row {
    float4 sl, sr, vl0, vl1, vl2, vr0, vr1, vr2;
};

__device__ __forceinline__ void load_row(const float4* __restrict__ z0l,
                                         const float4* __restrict__ z1l,
                                         const float4* __restrict__ z0r,
                                         const float4* __restrict__ z1r,
                                         int n, int r, Row& R)
{
    const float4* vl = z1l + (size_t)(n * 3) * RQ + r;
    const float4* vr = z1r + (size_t)(n * 3) * RQ + r;
    R.sl  = ld4(z0l + (size_t)n * RQ + r);
    R.sr  = ld4(z0r + (size_t)n * RQ + r);
    R.vl0 = ld4(vl + 0 * RQ);
    R.vl1 = ld4(vl + 1 * RQ);
    R.vl2 = ld4(vl + 2 * RQ);
    R.vr0 = ld4(vr + 0 * RQ);
    R.vr1 = ld4(vr + 1 * RQ);
    R.vr2 = ld4(vr + 2 * RQ);
}

__device__ __forceinline__ void store_row(float4* __restrict__ out,
                                          int n, int r, const Row& R)
{
    const float INV_SQRT2 = 0.7071067811865476f;
    float4* ob = out + (size_t)(n * 3) * OQ + r;
    // m = 0
    st4(ob + 0 * OQ + 0 * RQ, mul4(R.sl, R.vr0));
    st4(ob + 0 * OQ + 1 * RQ, mul4(R.vl0, R.sr));
    st4(ob + 0 * OQ + 2 * RQ, fms4(R.vl1, R.vr2, R.vl2, R.vr1, INV_SQRT2));
    // m = 1
    st4(ob + 1 * OQ + 0 * RQ, mul4(R.sl, R.vr1));
    st4(ob + 1 * OQ + 1 * RQ, mul4(R.vl1, R.sr));
    st4(ob + 1 * OQ + 2 * RQ, fms4(R.vl2, R.vr0, R.vl0, R.vr2, INV_SQRT2));
    // m = 2
    st4(ob + 2 * OQ + 0 * RQ, mul4(R.sl, R.vr2));
    st4(ob + 2 * OQ + 1 * RQ, mul4(R.vl2, R.sr));
    st4(ob + 2 * OQ + 2 * RQ, fms4(R.vl0, R.vr1, R.vl1, R.vr0, INV_SQRT2));
}

__global__ void __launch_bounds__(256)
etp_o1_kernel(const float4* __restrict__ z0l,
              const float4* __restrict__ z1l,
              const float4* __restrict__ z0r,
              const float4* __restrict__ z1r,
              float4* __restrict__ out,
              int N, int half_n)   // half_n = ceil(N/2)
{
    int idx = blockIdx.x * blockDim.x + threadIdx.x;
    int n0 = idx / RQ;            // 0 .. half_n-1  (compile-time shift, RQ=64)
    int r  = idx - n0 * RQ;
    if (n0 >= half_n) return;
    int n1 = n0 + half_n;

    // Front-batch both rows' loads for 16 outstanding LDG.128 per thread.
    Row R0, R1;
    bool has1 = (n1 < N);
    load_row(z0l, z1l, z0r, z1r, n0, r, R0);
    if (has1) load_row(z0l, z1l, z0r, z1r, n1, r, R1);

    store_row(out, n0, r, R0);
    if (has1) store_row(out, n1, r, R1);
}

extern "C" void kernel_launch(void* const* d_in, const int* in_sizes, int n_in,
                              void* d_out, int out_size) {
    const float4* z0l = (const float4*)d_in[0];
    const float4* z1l = (const float4*)d_in[1];
    const float4* z0r = (const float4*)d_in[2];
    const float4* z1r = (const float4*)d_in[3];
    float4* out = (float4*)d_out;

    int N = in_sizes[0] / RANK;            // 50000
    int half_n = (N + 1) / 2;              // 25000
    int n_total = half_n * RQ;             // threads needed
    int threads = 256;
    int blocks = (n_total + threads - 1) / threads;
    etp_o1_kernel<<<blocks, threads>>>(z0l, z1l, z0r, z1r, out, N, half_n);
}